// round 6
// baseline (speedup 1.0000x reference)
#include <cuda_runtime.h>

#define BB 16
#define LL 48000
#define WW 64
#define LWT 512
#define BL (BB*LL)

#define NC0 3000      // 48000/16 level-0 chunks per row
#define NCH (BB*NC0)  // all level-0 chunks
#define NR1 188       // ceil(3000/16)
#define NP1 3008      // 3000 padded
#define NR2 12        // ceil(188/16)

// Static device scratch (no allocation).
__device__ float g_s0[BL];           // level-0 inner sequential 16-scans
__device__ float g_t0[BB][NC0];      // level-0 chunk sums
__device__ float g_o0[BB][NC0];      // final exclusive offsets per level-0 chunk
__device__ float g_wtT[LWT * WW];    // wavetables transposed to (LWT, W)

__global__ void prep_wt(const float* __restrict__ wt) {
    int i = blockIdx.x * blockDim.x + threadIdx.x;
    if (i < WW * LWT) {
        int w = i >> 9;
        int p = i & (LWT - 1);
        g_wtT[p * WW + w] = wt[i];
    }
}

// Level 0: one thread per 16-chunk, sequential left-fold (reduce_window eval order).
__global__ __launch_bounds__(256) void seq_level0(const float* __restrict__ pitch) {
    int c = blockIdx.x * blockDim.x + threadIdx.x;    // global chunk id
    if (c >= NCH) return;
    const float4* p4 = (const float4*)(pitch + c * 16);
    float o[16];
    float s = 0.0f;                                   // init; 0+x0 exact
#pragma unroll
    for (int q = 0; q < 4; q++) {
        float4 v = __ldg(&p4[q]);
        s = __fadd_rn(s, __fmul_rn(0.032f, v.x)); o[q*4+0] = s;
        s = __fadd_rn(s, __fmul_rn(0.032f, v.y)); o[q*4+1] = s;
        s = __fadd_rn(s, __fmul_rn(0.032f, v.z)); o[q*4+2] = s;
        s = __fadd_rn(s, __fmul_rn(0.032f, v.w)); o[q*4+3] = s;
    }
    float4* d4 = (float4*)(g_s0 + c * 16);
#pragma unroll
    for (int q = 0; q < 4; q++)
        d4[q] = make_float4(o[q*4+0], o[q*4+1], o[q*4+2], o[q*4+3]);
    g_t0[c / NC0][c % NC0] = s;
}

// Levels 1..3 per batch row: ReduceWindowRewriter recursion with sequential inner scans.
__global__ __launch_bounds__(256) void seq_upper(void) {
    __shared__ float t0s[NP1];        // level-1 input (padded)
    __shared__ float s1[NP1];         // level-1 inner scans
    __shared__ float s2[NR2 * 16];    // level-2 inner scans (192)
    __shared__ float sc12[NR2];       // level-3 inclusive scan (base case, sequential)

    int b = blockIdx.x;
    int tid = threadIdx.x, nt = blockDim.x;

    for (int j = tid; j < NP1; j += nt)
        t0s[j] = (j < NC0) ? g_t0[b][j] : 0.0f;
    __syncthreads();

    // level 1: sequential scan within each 16-chunk of the 3008 (padded) chunk sums
    for (int k = tid; k < NR1; k += nt) {
        float s = 0.0f;
#pragma unroll
        for (int j = 0; j < 16; j++) {
            s = __fadd_rn(s, t0s[k * 16 + j]);
            s1[k * 16 + j] = s;
        }
    }
    __syncthreads();

    // level 2: row sums t1[k] = s1[16k+15] (k<188, pad to 192), sequential within 16-chunks
    for (int k = tid; k < NR2; k += nt) {
        float s = 0.0f;
#pragma unroll
        for (int j = 0; j < 16; j++) {
            int r = k * 16 + j;
            float v = (r < NR1) ? s1[r * 16 + 15] : 0.0f;
            s = __fadd_rn(s, v);
            s2[r < NR2 * 16 ? r : 0] = s;   // r always < 192 here
        }
    }
    __syncthreads();

    // level 3 base case (12 <= base_length): plain sequential scan of t2
    if (tid == 0) {
        float s = 0.0f;
#pragma unroll
        for (int k = 0; k < NR2; k++) {
            s = __fadd_rn(s, s2[k * 16 + 15]);
            sc12[k] = s;
        }
    }
    __syncthreads();

    // Combine back down and emit exclusive offsets for level-0 chunks:
    // scan188[k] = s2[k] (+) (k>=16 ? sc12[k/16-1] : 0)
    // scan3000[j] = s1[j] (+) (j>=16 ? scan188[j/16-1] : 0)
    // o0[c] = c ? scan3000[c-1] : 0
    for (int c = tid; c < NC0; c += nt) {
        float o;
        if (c == 0) o = 0.0f;
        else {
            int j = c - 1;
            float v = s1[j];
            if (j >= 16) {
                int k = (j >> 4) - 1;
                float sk = s2[k];
                if (k >= 16) sk = __fadd_rn(sc12[(k >> 4) - 1], sk);
                o = __fadd_rn(sk, v);
            } else o = v;
        }
        g_o0[b][c] = o;
    }
}

// Warp per (b,l): 256B coalesced attention read, L1-resident table gathers, shuffle reduce.
__global__ __launch_bounds__(256) void synth(const float* __restrict__ pitch,
                                             const float* __restrict__ env,
                                             const float* __restrict__ attn,
                                             float* __restrict__ out) {
    unsigned t = blockIdx.x * blockDim.x + threadIdx.x;
    unsigned wid = t >> 5;
    unsigned lane = t & 31u;
    if (wid >= BL) return;
    unsigned b = wid / LL;
    unsigned l = wid - b * LL;

    // cumsum[i] = inner_scan (+) chunk_offset (offset add matches ref's broadcast-add)
    float cum = __fadd_rn(g_o0[b][l >> 4], g_s0[wid]);
    // index = cumsum - increment[row 0]  (ref broadcasts batch-row 0; no FMA contraction)
    float r = __fsub_rn(cum, __fmul_rn(0.032f, pitch[l]));
    r = fmodf(r, 512.0f);                 // lax.rem (exact)
    if (r < 0.0f) r += 512.0f;            // jnp.remainder sign fix
    if (512.0f - r < 1e-5f) r = 0.0f;     // the where() fixup

    float lowf  = floorf(r);
    float alpha = __fsub_rn(r, lowf);     // exact
    int il = (int)lowf;
    int ih = (int)ceilf(r);
    if (ih >= LWT) ih = 0;                // ceil % 512

    float2 a  = ((const float2*)(attn + (size_t)wid * WW))[lane];
    float2 wl = ((const float2*)(g_wtT + il * WW))[lane];
    float2 wh = ((const float2*)(g_wtT + ih * WW))[lane];

    float wvx = __fadd_rn(wl.x, __fmul_rn(alpha, __fsub_rn(wh.x, wl.x)));
    float wvy = __fadd_rn(wl.y, __fmul_rn(alpha, __fsub_rn(wh.y, wl.y)));
    float s = a.x * wvx + a.y * wvy;

#pragma unroll
    for (int o = 16; o; o >>= 1)
        s += __shfl_xor_sync(0xffffffffu, s, o);

    if (lane == 0)
        out[wid] = s * env[wid];
}

extern "C" void kernel_launch(void* const* d_in, const int* in_sizes, int n_in,
                              void* d_out, int out_size) {
    const float* pitch = (const float*)d_in[0];
    const float* env   = (const float*)d_in[1];
    const float* attn  = (const float*)d_in[2];
    const float* wt    = (const float*)d_in[3];
    float* out = (float*)d_out;

    prep_wt<<<(WW * LWT + 255) / 256, 256>>>(wt);
    seq_level0<<<(NCH + 255) / 256, 256>>>(pitch);
    seq_upper<<<BB, 256>>>();
    synth<<<(BL * 32) / 256, 256>>>(pitch, env, attn, out);
}

// round 8
// speedup vs baseline: 2.9615x; 2.9615x over previous
#include <cuda_runtime.h>

#define BB 16
#define LL 48000
#define WW 64
#define LWT 512
#define BL (BB*LL)

#define NC0 3000      // 48000/16 level-0 chunks per row
#define NCH (BB*NC0)  // all level-0 chunks
#define NR1 188       // ceil(3000/16)
#define NP1 3008      // 3000 padded
#define NR2 12        // ceil(188/16)

// Static device scratch (no allocation).
__device__ float  g_s0[BL];           // level-0 inner sequential 16-scans
__device__ float  g_t0[BB][NC0];      // level-0 chunk sums
__device__ float  g_o0[BB][NC0];      // final exclusive offsets per level-0 chunk
__device__ float  g_wtT[LWT * WW];    // wavetables transposed to (LWT, W)
__device__ float2 g_ai[BL];           // per-element (alpha, il | ih<<16)

__global__ void prep_wt(const float* __restrict__ wt) {
    int i = blockIdx.x * blockDim.x + threadIdx.x;
    if (i < WW * LWT) {
        int w = i >> 9;
        int p = i & (LWT - 1);
        g_wtT[p * WW + w] = wt[i];
    }
}

// Level 0: one thread per 16-chunk, sequential left-fold (reduce_window eval order).
__global__ __launch_bounds__(256) void seq_level0(const float* __restrict__ pitch) {
    int c = blockIdx.x * blockDim.x + threadIdx.x;    // global chunk id
    if (c >= NCH) return;
    const float4* p4 = (const float4*)(pitch + c * 16);
    float o[16];
    float s = 0.0f;                                   // init; 0+x0 exact
#pragma unroll
    for (int q = 0; q < 4; q++) {
        float4 v = __ldg(&p4[q]);
        s = __fadd_rn(s, __fmul_rn(0.032f, v.x)); o[q*4+0] = s;
        s = __fadd_rn(s, __fmul_rn(0.032f, v.y)); o[q*4+1] = s;
        s = __fadd_rn(s, __fmul_rn(0.032f, v.z)); o[q*4+2] = s;
        s = __fadd_rn(s, __fmul_rn(0.032f, v.w)); o[q*4+3] = s;
    }
    float4* d4 = (float4*)(g_s0 + c * 16);
#pragma unroll
    for (int q = 0; q < 4; q++)
        d4[q] = make_float4(o[q*4+0], o[q*4+1], o[q*4+2], o[q*4+3]);
    g_t0[c / NC0][c % NC0] = s;
}

// Levels 1..3 per batch row: ReduceWindowRewriter recursion with sequential inner scans.
__global__ __launch_bounds__(256) void seq_upper(void) {
    __shared__ float t0s[NP1];        // level-1 input (padded)
    __shared__ float s1[NP1];         // level-1 inner scans
    __shared__ float s2[NR2 * 16];    // level-2 inner scans (192)
    __shared__ float sc12[NR2];       // level-3 inclusive scan (base case, sequential)

    int b = blockIdx.x;
    int tid = threadIdx.x, nt = blockDim.x;

    for (int j = tid; j < NP1; j += nt)
        t0s[j] = (j < NC0) ? g_t0[b][j] : 0.0f;
    __syncthreads();

    for (int k = tid; k < NR1; k += nt) {
        float s = 0.0f;
#pragma unroll
        for (int j = 0; j < 16; j++) {
            s = __fadd_rn(s, t0s[k * 16 + j]);
            s1[k * 16 + j] = s;
        }
    }
    __syncthreads();

    for (int k = tid; k < NR2; k += nt) {
        float s = 0.0f;
#pragma unroll
        for (int j = 0; j < 16; j++) {
            int r = k * 16 + j;
            float v = (r < NR1) ? s1[r * 16 + 15] : 0.0f;
            s = __fadd_rn(s, v);
            s2[r] = s;
        }
    }
    __syncthreads();

    if (tid == 0) {
        float s = 0.0f;
#pragma unroll
        for (int k = 0; k < NR2; k++) {
            s = __fadd_rn(s, s2[k * 16 + 15]);
            sc12[k] = s;
        }
    }
    __syncthreads();

    for (int c = tid; c < NC0; c += nt) {
        float o;
        if (c == 0) o = 0.0f;
        else {
            int j = c - 1;
            float v = s1[j];
            if (j >= 16) {
                int k = (j >> 4) - 1;
                float sk = s2[k];
                if (k >= 16) sk = __fadd_rn(sc12[(k >> 4) - 1], sk);
                o = __fadd_rn(sk, v);
            } else o = v;
        }
        g_o0[b][c] = o;
    }
}

// Per-element index math, hoisted out of synth. Bitwise identical to the R4 path.
__global__ __launch_bounds__(256) void finalize_idx(const float* __restrict__ pitch) {
    int i = blockIdx.x * blockDim.x + threadIdx.x;
    if (i >= BL) return;
    int b = i / LL;
    int l = i - b * LL;

    float cum = __fadd_rn(g_o0[b][l >> 4], g_s0[i]);
    float r = __fsub_rn(cum, __fmul_rn(0.032f, pitch[l]));  // ref subtracts batch-row-0 increment
    r = fmodf(r, 512.0f);                 // lax.rem (exact)
    if (r < 0.0f) r += 512.0f;            // jnp.remainder sign fix
    if (512.0f - r < 1e-5f) r = 0.0f;     // the where() fixup

    float lowf  = floorf(r);
    float alpha = __fsub_rn(r, lowf);     // exact
    int il = (int)lowf;
    int ih = (int)ceilf(r);
    if (ih >= LWT) ih = 0;                // ceil % 512

    g_ai[i] = make_float2(alpha, __uint_as_float((unsigned)il | ((unsigned)ih << 16)));
}

// Synth: 4 lanes per element, 16 attn values (4 x float4) per lane.
// out = (L + alpha*(H - L)) * env, with L = attn.wl, H = attn.wh (dots).
__global__ __launch_bounds__(256) void synth(const float* __restrict__ env,
                                             const float* __restrict__ attn,
                                             float* __restrict__ out) {
    unsigned t    = blockIdx.x * blockDim.x + threadIdx.x;
    unsigned warp = t >> 5;
    unsigned lane = t & 31u;
    unsigned g    = lane >> 2;            // element slot within warp (0..7)
    unsigned sub  = lane & 3u;            // lane within element (0..3)
    unsigned e    = warp * 8 + g;         // element id
    if (e >= BL) return;                  // guard (grid is exact, but keep it safe)

    float2 ai = __ldg(&g_ai[e]);
    unsigned v = __float_as_uint(ai.y);
    unsigned il = v & 0xffffu;
    unsigned ih = v >> 16;

    const float4* a4  = (const float4*)attn + (size_t)e * 16 + sub;
    const float4* wl4 = (const float4*)g_wtT + il * 16 + sub;
    const float4* wh4 = (const float4*)g_wtT + ih * 16 + sub;

    float accL = 0.0f, accH = 0.0f;
#pragma unroll
    for (int q = 0; q < 4; q++) {         // lane covers w = q*16 + sub*4 + [0..3]
        float4 a  = __ldg(a4  + q * 4);
        float4 wl = __ldg(wl4 + q * 4);
        float4 wh = __ldg(wh4 + q * 4);
        accL += a.x * wl.x + a.y * wl.y + a.z * wl.z + a.w * wl.w;
        accH += a.x * wh.x + a.y * wh.y + a.z * wh.z + a.w * wh.w;
    }

    // reduce over the 4 lanes of this element
    accL += __shfl_xor_sync(0xffffffffu, accL, 1);
    accH += __shfl_xor_sync(0xffffffffu, accH, 1);
    accL += __shfl_xor_sync(0xffffffffu, accL, 2);
    accH += __shfl_xor_sync(0xffffffffu, accH, 2);

    if (sub == 0) {
        float s = accL + ai.x * (accH - accL);
        out[e] = s * __ldg(&env[e]);
    }
}

extern "C" void kernel_launch(void* const* d_in, const int* in_sizes, int n_in,
                              void* d_out, int out_size) {
    const float* pitch = (const float*)d_in[0];
    const float* env   = (const float*)d_in[1];
    const float* attn  = (const float*)d_in[2];
    const float* wt    = (const float*)d_in[3];
    float* out = (float*)d_out;

    prep_wt<<<(WW * LWT + 255) / 256, 256>>>(wt);
    seq_level0<<<(NCH + 255) / 256, 256>>>(pitch);
    seq_upper<<<BB, 256>>>();
    finalize_idx<<<(BL + 255) / 256, 256>>>(pitch);
    synth<<<(BL * 4) / 256, 256>>>(env, attn, out);   // BL elements x 4 lanes = 12000 blocks
}